// round 3
// baseline (speedup 1.0000x reference)
#include <cuda_runtime.h>
#include <math.h>

#define RUNS 512
#define WAYS 5
#define NSUP 25
#define NQ   75
#define NTOT 100
#define NEXTN 105
#define DD   640
#define EPSf 0.001f

// ---------------- device scratch (static, no allocation) ----------------
__device__ float g_proto[RUNS*WAYS*DD];
__device__ float g_addp [RUNS*WAYS*DD];
__device__ float g_M [RUNS*NEXTN*WAYS];   // sinkhorn input
__device__ float g_Z [RUNS*NEXTN*WAYS];   // current Z
__device__ float g_ent[RUNS*NTOT];
__device__ float g_W [RUNS*NEXTN*NEXTN];  // graph weights
__device__ float g_dm [RUNS*NEXTN];       // D^-1/2
__device__ float g_sqn[RUNS*NEXTN];       // squared norms of features105
__device__ int   g_iters;

__constant__ int TIt[10] = {0,0,0,0,1,1,1,2,2,3};
__constant__ int TJt[10] = {0,1,2,3,1,2,3,2,3,3};

// ---------------- helpers ----------------
__device__ __forceinline__ const float* frow(const float* xs, const float* xq, int b, int i) {
    if (i < NSUP) return xs + ((size_t)b*NSUP + i)*DD;
    if (i < NTOT) return xq + ((size_t)b*NQ + (i-NSUP))*DD;
    return g_addp + ((size_t)b*WAYS + (i-NTOT))*DD;
}

__device__ __forceinline__ float entropy5(const float* v) {
    float p[5]; float s = 0.f;
    #pragma unroll
    for (int k = 0; k < 5; k++) { p[k] = v[k] + 1e-12f; s += p[k]; }
    float H = 0.f;
    #pragma unroll
    for (int k = 0; k < 5; k++) { float q = p[k]/s; H -= q*logf(q); }
    return H / logf(5.0f);
}

// ---------------- proto init: mean over shots ----------------
__global__ void k_proto_init(const float* __restrict__ xs) {
    int b = blockIdx.x, d = threadIdx.x;   // 640 threads
    #pragma unroll
    for (int k = 0; k < WAYS; k++) {
        float s = 0.f;
        #pragma unroll
        for (int sh = 0; sh < 5; sh++) s += xs[((size_t)b*NSUP + k*5 + sh)*DD + d];
        g_proto[((size_t)b*WAYS + k)*DD + d] = s / 5.0f;
    }
}

// ---------------- Pq = exp(-10 * d2(query, proto)) ----------------
__global__ void k_pq(const float* __restrict__ xq) {
    int gw = (blockIdx.x*blockDim.x + threadIdx.x) >> 5;
    int lane = threadIdx.x & 31;
    if (gw >= RUNS*NQ) return;
    int b = gw / NQ, q = gw % NQ;
    const float* x  = xq + ((size_t)b*NQ + q)*DD;
    const float* pr = g_proto + (size_t)b*WAYS*DD;
    float dot[5] = {0,0,0,0,0}, pp[5] = {0,0,0,0,0}, qq = 0.f;
    for (int d = lane; d < DD; d += 32) {
        float xv = x[d];
        qq += xv*xv;
        #pragma unroll
        for (int k = 0; k < 5; k++) {
            float pv = pr[k*DD + d];
            dot[k] += xv*pv;
            pp[k]  += pv*pv;
        }
    }
    #pragma unroll
    for (int off = 16; off; off >>= 1) {
        qq += __shfl_xor_sync(0xffffffffu, qq, off);
        #pragma unroll
        for (int k = 0; k < 5; k++) {
            dot[k] += __shfl_xor_sync(0xffffffffu, dot[k], off);
            pp[k]  += __shfl_xor_sync(0xffffffffu, pp[k],  off);
        }
    }
    if (lane == 0) {
        #pragma unroll
        for (int k = 0; k < 5; k++) {
            float d2 = qq + pp[k] - 2.0f*dot[k];
            d2 = fmaxf(d2, 0.0f);
            g_M[((size_t)b*NEXTN + q)*WAYS + k] = expf(-10.0f*d2);
        }
    }
}

__global__ void k_reset() { g_iters = 0; }

// ---------------- warp-resident sinkhorn ----------------
// T < 0: count mode (per-run convergence count, cond checked BEFORE body).
// T >= 0: replay exactly T body executions.
template<int N, bool CLAMP>
__device__ __forceinline__ int sink_iter(float (&P)[(N+31)/32][WAYS], int b, int lane,
                                         const int* ys, float Cval, int T) {
    const int RPT = (N+31)/32;
    float u[RPT];
    #pragma unroll
    for (int r = 0; r < RPT; r++) u[r] = 0.f;
    int K = 0;
    while (true) {
        if (T >= 0 && K >= T) break;
        float rs[RPT];
        #pragma unroll
        for (int r = 0; r < RPT; r++) {
            int row = lane + 32*r;
            rs[r] = (row < N) ? ((((P[r][0]+P[r][1])+P[r][2])+P[r][3])+P[r][4]) : 0.f;
        }
        if (T < 0) {
            float rm = 0.f;
            #pragma unroll
            for (int r = 0; r < RPT; r++) {
                int row = lane + 32*r;
                if (row < N) rm = fmaxf(rm, fabsf(u[r]-rs[r]));
            }
            #pragma unroll
            for (int off = 16; off; off >>= 1)
                rm = fmaxf(rm, __shfl_xor_sync(0xffffffffu, rm, off));
            if (rm <= EPSf || K >= 1000) break;
            #pragma unroll
            for (int r = 0; r < RPT; r++) u[r] = rs[r];
        }
        // body: row normalize (r=1), col normalize to c, clamp labels
        #pragma unroll
        for (int r = 0; r < RPT; r++) {
            int row = lane + 32*r;
            if (row < N) {
                float inv = 1.0f/rs[r];
                #pragma unroll
                for (int k = 0; k < WAYS; k++) P[r][k] *= inv;
            }
        }
        float cs[WAYS];
        #pragma unroll
        for (int k = 0; k < WAYS; k++) cs[k] = 0.f;
        #pragma unroll
        for (int r = 0; r < RPT; r++) {
            int row = lane + 32*r;
            if (row < N) {
                #pragma unroll
                for (int k = 0; k < WAYS; k++) cs[k] += P[r][k];
            }
        }
        #pragma unroll
        for (int off = 16; off; off >>= 1) {
            #pragma unroll
            for (int k = 0; k < WAYS; k++)
                cs[k] += __shfl_xor_sync(0xffffffffu, cs[k], off);
        }
        #pragma unroll
        for (int k = 0; k < WAYS; k++) cs[k] = Cval/cs[k];
        #pragma unroll
        for (int r = 0; r < RPT; r++) {
            int row = lane + 32*r;
            if (row < N) {
                #pragma unroll
                for (int k = 0; k < WAYS; k++) P[r][k] *= cs[k];
            }
        }
        if (CLAMP) {
            #pragma unroll
            for (int r = 0; r < RPT; r++) {
                int row = lane + 32*r;
                if (row < NSUP) {
                    int y = ys[b*NSUP + row];
                    #pragma unroll
                    for (int k = 0; k < WAYS; k++) P[r][k] = (k == y) ? 1.0f : 0.0f;
                }
            }
        }
        K++;
    }
    return K;
}

__global__ void k_sink1_count() {
    int gw = (blockIdx.x*blockDim.x + threadIdx.x) >> 5;
    int lane = threadIdx.x & 31;
    if (gw >= RUNS) return;
    float P[3][WAYS];
    const float* Mb = g_M + (size_t)gw*NEXTN*WAYS;
    #pragma unroll
    for (int r = 0; r < 3; r++) {
        int row = lane + 32*r;
        #pragma unroll
        for (int k = 0; k < WAYS; k++) P[r][k] = (row < NQ) ? Mb[row*WAYS + k] : 0.f;
    }
    int K = sink_iter<NQ, false>(P, gw, lane, nullptr, 15.0f, -1);
    if (lane == 0) atomicMax(&g_iters, K);
}

__global__ void k_sink1_apply(const int* __restrict__ ys) {
    int gw = (blockIdx.x*blockDim.x + threadIdx.x) >> 5;
    int lane = threadIdx.x & 31;
    if (gw >= RUNS) return;
    int b = gw;
    float P[3][WAYS];
    const float* Mb = g_M + (size_t)b*NEXTN*WAYS;
    #pragma unroll
    for (int r = 0; r < 3; r++) {
        int row = lane + 32*r;
        #pragma unroll
        for (int k = 0; k < WAYS; k++) P[r][k] = (row < NQ) ? Mb[row*WAYS + k] : 0.f;
    }
    int T = g_iters;
    sink_iter<NQ, false>(P, b, lane, nullptr, 15.0f, T);
    // queries: entropy, weight, write Z rows 25..99
    #pragma unroll
    for (int r = 0; r < 3; r++) {
        int row = lane + 32*r;
        if (row < NQ) {
            float e = entropy5(&P[r][0]);
            g_ent[b*NTOT + NSUP + row] = e;
            float wgt = 1.0f - e;
            #pragma unroll
            for (int k = 0; k < WAYS; k++)
                g_Z[((size_t)b*NEXTN + NSUP + row)*WAYS + k] = P[r][k]*wgt;
        }
    }
    // support: onehot, entropy, weight, write Z rows 0..24
    if (lane < NSUP) {
        int y = ys[b*NSUP + lane];
        float v[5];
        #pragma unroll
        for (int k = 0; k < WAYS; k++) v[k] = (k == y) ? 1.0f : 0.0f;
        float e = entropy5(v);
        g_ent[b*NTOT + lane] = e;
        float wgt = 1.0f - e;
        #pragma unroll
        for (int k = 0; k < WAYS; k++)
            g_Z[((size_t)b*NEXTN + lane)*WAYS + k] = v[k]*wgt;
    }
}

__global__ void k_sink2_count(const int* __restrict__ ys) {
    int gw = (blockIdx.x*blockDim.x + threadIdx.x) >> 5;
    int lane = threadIdx.x & 31;
    if (gw >= RUNS) return;
    float P[4][WAYS];
    const float* Mb = g_M + (size_t)gw*NEXTN*WAYS;
    #pragma unroll
    for (int r = 0; r < 4; r++) {
        int row = lane + 32*r;
        #pragma unroll
        for (int k = 0; k < WAYS; k++) P[r][k] = (row < NEXTN) ? Mb[row*WAYS + k] : 0.f;
    }
    int K = sink_iter<NEXTN, true>(P, gw, lane, ys, 21.0f, -1);
    if (lane == 0) atomicMax(&g_iters, K);
}

__global__ void k_sink2_apply(const int* __restrict__ ys) {
    int gw = (blockIdx.x*blockDim.x + threadIdx.x) >> 5;
    int lane = threadIdx.x & 31;
    if (gw >= RUNS) return;
    int b = gw;
    float P[4][WAYS];
    const float* Mb = g_M + (size_t)b*NEXTN*WAYS;
    #pragma unroll
    for (int r = 0; r < 4; r++) {
        int row = lane + 32*r;
        #pragma unroll
        for (int k = 0; k < WAYS; k++) P[r][k] = (row < NEXTN) ? Mb[row*WAYS + k] : 0.f;
    }
    int T = g_iters;
    sink_iter<NEXTN, true>(P, b, lane, ys, 21.0f, T);
    #pragma unroll
    for (int r = 0; r < 4; r++) {
        int row = lane + 32*r;
        if (row < NEXTN) {
            #pragma unroll
            for (int k = 0; k < WAYS; k++)
                g_Z[((size_t)b*NEXTN + row)*WAYS + k] = P[r][k];
        }
    }
}

// ---------------- new_proto + proto EMA update ----------------
__global__ void k_newproto(const float* __restrict__ xs, const float* __restrict__ xq) {
    int b = blockIdx.x, t = threadIdx.x;  // 640 threads
    __shared__ float Zs[NTOT*WAYS];
    __shared__ float cs[WAYS];
    for (int idx = t; idx < NTOT*WAYS; idx += blockDim.x)
        Zs[idx] = g_Z[(size_t)b*NEXTN*WAYS + idx];
    __syncthreads();
    if (t < WAYS) {
        float s = 0.f;
        for (int n = 0; n < NTOT; n++) s += Zs[n*WAYS + t];
        cs[t] = s;
    }
    __syncthreads();
    float acc[WAYS] = {0,0,0,0,0};
    for (int n = 0; n < NTOT; n++) {
        float f = frow(xs, xq, b, n)[t];
        #pragma unroll
        for (int k = 0; k < WAYS; k++) acc[k] += Zs[n*WAYS + k]*f;
    }
    #pragma unroll
    for (int k = 0; k < WAYS; k++) {
        size_t pi = ((size_t)b*WAYS + k)*DD + t;
        float np = acc[k]/cs[k];
        g_proto[pi] = 0.4f*g_proto[pi] + 0.6f*np;
    }
}

// ---------------- epoch-2: proto mask, add_proto, Z extension ----------------
__global__ void k_mask() {
    int b = blockIdx.x, t = threadIdx.x;   // 160 threads
    int w = t >> 5, lane = t & 31;
    __shared__ float nrm[5], dp[5][5], score[5], mk[5], omega_s;
    const float* pr = g_proto + (size_t)b*WAYS*DD;
    {
        float a = 0.f;
        for (int d = lane; d < DD; d += 32) { float v = pr[w*DD + d]; a += v*v; }
        #pragma unroll
        for (int off = 16; off; off >>= 1) a += __shfl_xor_sync(0xffffffffu, a, off);
        if (lane == 0) nrm[w] = a;
    }
    __syncthreads();
    for (int j = 0; j < 5; j++) {
        float s = 0.f;
        for (int d = lane; d < DD; d += 32) s += pr[w*DD + d]*pr[j*DD + d];
        #pragma unroll
        for (int off = 16; off; off >>= 1) s += __shfl_xor_sync(0xffffffffu, s, off);
        if (lane == 0) {
            float d2 = fmaxf(nrm[w] + nrm[j] - 2.0f*s, 0.0f);
            dp[w][j] = expf(-10.0f*d2);
        }
    }
    __syncthreads();
    if (t < 5) score[t] = entropy5(&dp[t][0]);
    if (w == 1) {
        float s = 0.f;
        for (int i = lane; i < NTOT; i += 32) s += g_ent[b*NTOT + i];
        #pragma unroll
        for (int off = 16; off; off >>= 1) s += __shfl_xor_sync(0xffffffffu, s, off);
        if (lane == 0) omega_s = s / 100.0f;
    }
    __syncthreads();
    if (t < 5) mk[t] = (score[t] < omega_s) ? 1.0f : 0.0f;
    __syncthreads();
    for (int idx = t; idx < WAYS*DD; idx += 160) {
        int i = idx / DD, d = idx % DD;
        g_addp[((size_t)b*WAYS + i)*DD + d] = pr[i*DD + d]*mk[i];
    }
    if (t < 25) {
        int i = t / 5, k = t % 5;
        g_Z[((size_t)b*NEXTN + NTOT + i)*WAYS + k] = dp[i][k]*mk[i];
    }
}

// ---------------- squared norms of 105 feature rows ----------------
__global__ void k_sqn(const float* __restrict__ xs, const float* __restrict__ xq) {
    int b = blockIdx.x;
    int w = threadIdx.x >> 5, lane = threadIdx.x & 31;
    for (int row = w; row < NEXTN; row += 4) {
        const float* f = frow(xs, xq, b, row);
        float s = 0.f;
        for (int d = lane; d < DD; d += 32) { float v = f[d]; s += v*v; }
        #pragma unroll
        for (int off = 16; off; off >>= 1) s += __shfl_xor_sync(0xffffffffu, s, off);
        if (lane == 0) g_sqn[b*NEXTN + row] = s;
    }
}

// ---------------- 105x105 Gram -> W = exp(-10 d2), zero diag ----------------
__global__ void k_gram(const float* __restrict__ xs, const float* __restrict__ xq) {
    int b  = blockIdx.y;
    int ti = TIt[blockIdx.x], tj = TJt[blockIdx.x];
    int tx = threadIdx.x, ty = threadIdx.y;       // 16x16
    int t  = ty*16 + tx;
    __shared__ float As[32][33], Bs[32][33];
    float acc00=0,acc01=0,acc10=0,acc11=0;
    for (int dc = 0; dc < DD; dc += 32) {
        #pragma unroll
        for (int l = 0; l < 4; l++) {
            int e = t + l*256, r = e >> 5, c = e & 31;
            int gi = ti*32 + r, gj = tj*32 + r;
            As[r][c] = (gi < NEXTN) ? frow(xs, xq, b, gi)[dc + c] : 0.f;
            Bs[r][c] = (gj < NEXTN) ? frow(xs, xq, b, gj)[dc + c] : 0.f;
        }
        __syncthreads();
        #pragma unroll
        for (int kk = 0; kk < 32; kk++) {
            float a0 = As[ty][kk], a1 = As[ty+16][kk];
            float b0 = Bs[tx][kk], b1 = Bs[tx+16][kk];
            acc00 += a0*b0; acc01 += a0*b1;
            acc10 += a1*b0; acc11 += a1*b1;
        }
        __syncthreads();
    }
    size_t Wb = (size_t)b*NEXTN*NEXTN;
    float accs[2][2] = {{acc00,acc01},{acc10,acc11}};
    #pragma unroll
    for (int ry = 0; ry < 2; ry++)
    #pragma unroll
    for (int rx = 0; rx < 2; rx++) {
        int i = ti*32 + ry*16 + ty, j = tj*32 + rx*16 + tx;
        if (i < NEXTN && j < NEXTN) {
            float d2 = g_sqn[b*NEXTN + i] + g_sqn[b*NEXTN + j] - 2.0f*accs[ry][rx];
            d2 = fmaxf(d2, 0.0f);
            float wv = (i == j) ? 0.0f : expf(-10.0f*d2);
            g_W[Wb + (size_t)i*NEXTN + j] = wv;
            if (ti != tj) g_W[Wb + (size_t)j*NEXTN + i] = wv;
        }
    }
}

// ---------------- Dm = rowsum^-1/2 ----------------
__global__ void k_dm() {
    int b = blockIdx.x;
    int w = threadIdx.x >> 5, lane = threadIdx.x & 31;
    for (int row = w; row < NEXTN; row += 4) {
        const float* Wr = g_W + (size_t)b*NEXTN*NEXTN + (size_t)row*NEXTN;
        float s = 0.f;
        for (int j = lane; j < NEXTN; j += 32) s += Wr[j];
        #pragma unroll
        for (int off = 16; off; off >>= 1) s += __shfl_xor_sync(0xffffffffu, s, off);
        if (lane == 0) g_dm[b*NEXTN + row] = 1.0f/sqrtf(s);
    }
}

// ---------------- solve (I - 0.7 * Dm W Dm) X = Z  -> g_M ----------------
__global__ void __launch_bounds__(128) k_solve() {
    int b = blockIdx.x, t = threadIdx.x;
    __shared__ float A[NEXTN*112];
    const float* Wb = g_W + (size_t)b*NEXTN*NEXTN;
    const float* dm = g_dm + b*NEXTN;
    for (int idx = t; idx < NEXTN*NEXTN; idx += 128) {
        int i = idx/NEXTN, j = idx%NEXTN;
        float wn = dm[i]*Wb[idx]*dm[j];
        A[i*112 + j] = ((i == j) ? 1.0f : 0.0f) - 0.7f*wn;
    }
    for (int idx = t; idx < NEXTN*WAYS; idx += 128) {
        int i = idx/WAYS, k = idx%WAYS;
        A[i*112 + NEXTN + k] = g_Z[((size_t)b*NEXTN + i)*WAYS + k];
    }
    __syncthreads();
    for (int k = 0; k < NEXTN; k++) {
        if (t < NEXTN && t != k) {
            float f = A[t*112 + k] / A[k*112 + k];
            for (int j = k+1; j < NEXTN + WAYS; j++)
                A[t*112 + j] -= f*A[k*112 + j];
        }
        __syncthreads();
    }
    for (int idx = t; idx < NEXTN*WAYS; idx += 128) {
        int i = idx/WAYS, k = idx%WAYS;
        g_M[((size_t)b*NEXTN + i)*WAYS + k] = A[i*112 + NEXTN + k] / A[i*112 + i];
    }
}

// ---------------- predict: argmax over query rows, compare yq ----------------
__global__ void k_predict(const int* __restrict__ yq, float* __restrict__ out) {
    int gw = (blockIdx.x*blockDim.x + threadIdx.x) >> 5;
    int lane = threadIdx.x & 31;
    if (gw >= RUNS) return;
    int cnt = 0;
    for (int q = lane; q < NQ; q += 32) {
        const float* z = g_Z + ((size_t)gw*NEXTN + NSUP + q)*WAYS;
        int am = 0; float bv = z[0];
        #pragma unroll
        for (int k = 1; k < 5; k++) { float v = z[k]; if (v > bv) { bv = v; am = k; } }
        cnt += (am == yq[gw*NQ + q]) ? 1 : 0;
    }
    #pragma unroll
    for (int off = 16; off; off >>= 1) cnt += __shfl_xor_sync(0xffffffffu, cnt, off);
    if (lane == 0) out[gw] = (float)cnt / 75.0f;
}

extern "C" void kernel_launch(void* const* d_in, const int* in_sizes, int n_in,
                              void* d_out, int out_size) {
    const float* xs = (const float*)d_in[0];
    const float* xq = (const float*)d_in[1];
    const int*   ys = (const int*)d_in[2];
    const int*   yq = (const int*)d_in[3];
    float* out = (float*)d_out;

    k_proto_init<<<RUNS, DD>>>(xs);
    for (int e = 0; e < 3; e++) {
        k_pq<<<(RUNS*NQ*32 + 255)/256, 256>>>(xq);
        k_reset<<<1, 1>>>();
        k_sink1_count<<<(RUNS*32 + 255)/256, 256>>>();
        k_sink1_apply<<<(RUNS*32 + 255)/256, 256>>>(ys);
        k_newproto<<<RUNS, DD>>>(xs, xq);
        if (e == 2) {
            k_mask<<<RUNS, 160>>>();
            k_sqn<<<RUNS, 128>>>(xs, xq);
            k_gram<<<dim3(10, RUNS), dim3(16, 16)>>>(xs, xq);
            k_dm<<<RUNS, 128>>>();
            k_solve<<<RUNS, 128>>>();
            k_reset<<<1, 1>>>();
            k_sink2_count<<<(RUNS*32 + 255)/256, 256>>>(ys);
            k_sink2_apply<<<(RUNS*32 + 255)/256, 256>>>(ys);
            k_predict<<<(RUNS*32 + 255)/256, 256>>>(yq, out);
        }
    }
}

// round 6
// speedup vs baseline: 2.5171x; 2.5171x over previous
#include <cuda_runtime.h>
#include <math.h>

#define RUNS 512
#define WAYS 5
#define NSUP 25
#define NQ   75
#define NTOT 100
#define NEXTN 105
#define DD   640
#define EPSf 0.001f
#define LDA 113   // padded row stride for solve (odd -> conflict-free)

// ---------------- device scratch (static, no allocation) ----------------
__device__ float g_proto[RUNS*WAYS*DD];
__device__ float g_addp [RUNS*WAYS*DD];
__device__ float g_M [RUNS*NEXTN*WAYS];   // sinkhorn input
__device__ float g_Z [RUNS*NEXTN*WAYS];   // current Z
__device__ float g_ent[RUNS*NTOT];
__device__ float g_W [RUNS*NEXTN*NEXTN];  // graph weights
__device__ float g_dm [RUNS*NEXTN];       // D^-1/2
__device__ float g_sqn[RUNS*NEXTN];       // squared norms of features105
__device__ int   g_iters;

__constant__ int TIt[10] = {0,0,0,0,1,1,1,2,2,3};
__constant__ int TJt[10] = {0,1,2,3,1,2,3,2,3,3};

// ---------------- helpers ----------------
__device__ __forceinline__ const float* frow(const float* xs, const float* xq, int b, int i) {
    if (i < NSUP) return xs + ((size_t)b*NSUP + i)*DD;
    if (i < NTOT) return xq + ((size_t)b*NQ + (i-NSUP))*DD;
    return g_addp + ((size_t)b*WAYS + (i-NTOT))*DD;
}

__device__ __forceinline__ float entropy5(const float* v) {
    float p[5]; float s = 0.f;
    #pragma unroll
    for (int k = 0; k < 5; k++) { p[k] = v[k] + 1e-12f; s += p[k]; }
    float H = 0.f;
    #pragma unroll
    for (int k = 0; k < 5; k++) { float q = p[k]/s; H -= q*logf(q); }
    return H / logf(5.0f);
}

// ---------------- proto init: mean over shots ----------------
__global__ void k_proto_init(const float* __restrict__ xs) {
    int b = blockIdx.x, d = threadIdx.x;   // 640 threads
    #pragma unroll
    for (int k = 0; k < WAYS; k++) {
        float s = 0.f;
        #pragma unroll
        for (int sh = 0; sh < 5; sh++) s += xs[((size_t)b*NSUP + k*5 + sh)*DD + d];
        g_proto[((size_t)b*WAYS + k)*DD + d] = s / 5.0f;
    }
}

// ---------------- Pq = exp(-10 * d2(query, proto)) ----------------
__global__ void k_pq(const float* __restrict__ xq) {
    int gw = (blockIdx.x*blockDim.x + threadIdx.x) >> 5;
    int lane = threadIdx.x & 31;
    if (gw >= RUNS*NQ) return;
    int b = gw / NQ, q = gw % NQ;
    const float* x  = xq + ((size_t)b*NQ + q)*DD;
    const float* pr = g_proto + (size_t)b*WAYS*DD;
    float dot[5] = {0,0,0,0,0}, pp[5] = {0,0,0,0,0}, qq = 0.f;
    for (int d = lane; d < DD; d += 32) {
        float xv = x[d];
        qq += xv*xv;
        #pragma unroll
        for (int k = 0; k < 5; k++) {
            float pv = pr[k*DD + d];
            dot[k] += xv*pv;
            pp[k]  += pv*pv;
        }
    }
    #pragma unroll
    for (int off = 16; off; off >>= 1) {
        qq += __shfl_xor_sync(0xffffffffu, qq, off);
        #pragma unroll
        for (int k = 0; k < 5; k++) {
            dot[k] += __shfl_xor_sync(0xffffffffu, dot[k], off);
            pp[k]  += __shfl_xor_sync(0xffffffffu, pp[k],  off);
        }
    }
    if (lane == 0) {
        #pragma unroll
        for (int k = 0; k < 5; k++) {
            float d2 = qq + pp[k] - 2.0f*dot[k];
            d2 = fmaxf(d2, 0.0f);
            g_M[((size_t)b*NEXTN + q)*WAYS + k] = expf(-10.0f*d2);
        }
    }
}

__global__ void k_reset() { g_iters = 0; }

// ---------------- warp-resident sinkhorn ----------------
template<int N, bool CLAMP>
__device__ __forceinline__ int sink_iter(float (&P)[(N+31)/32][WAYS], int b, int lane,
                                         const int* ys, float Cval, int T) {
    const int RPT = (N+31)/32;
    float u[RPT];
    #pragma unroll
    for (int r = 0; r < RPT; r++) u[r] = 0.f;
    int K = 0;
    while (true) {
        if (T >= 0 && K >= T) break;
        float rs[RPT];
        #pragma unroll
        for (int r = 0; r < RPT; r++) {
            int row = lane + 32*r;
            rs[r] = (row < N) ? ((((P[r][0]+P[r][1])+P[r][2])+P[r][3])+P[r][4]) : 0.f;
        }
        if (T < 0) {
            float rm = 0.f;
            #pragma unroll
            for (int r = 0; r < RPT; r++) {
                int row = lane + 32*r;
                if (row < N) rm = fmaxf(rm, fabsf(u[r]-rs[r]));
            }
            #pragma unroll
            for (int off = 16; off; off >>= 1)
                rm = fmaxf(rm, __shfl_xor_sync(0xffffffffu, rm, off));
            if (rm <= EPSf || K >= 1000) break;
            #pragma unroll
            for (int r = 0; r < RPT; r++) u[r] = rs[r];
        }
        #pragma unroll
        for (int r = 0; r < RPT; r++) {
            int row = lane + 32*r;
            if (row < N) {
                float inv = 1.0f/rs[r];
                #pragma unroll
                for (int k = 0; k < WAYS; k++) P[r][k] *= inv;
            }
        }
        float cs[WAYS];
        #pragma unroll
        for (int k = 0; k < WAYS; k++) cs[k] = 0.f;
        #pragma unroll
        for (int r = 0; r < RPT; r++) {
            int row = lane + 32*r;
            if (row < N) {
                #pragma unroll
                for (int k = 0; k < WAYS; k++) cs[k] += P[r][k];
            }
        }
        #pragma unroll
        for (int off = 16; off; off >>= 1) {
            #pragma unroll
            for (int k = 0; k < WAYS; k++)
                cs[k] += __shfl_xor_sync(0xffffffffu, cs[k], off);
        }
        #pragma unroll
        for (int k = 0; k < WAYS; k++) cs[k] = Cval/cs[k];
        #pragma unroll
        for (int r = 0; r < RPT; r++) {
            int row = lane + 32*r;
            if (row < N) {
                #pragma unroll
                for (int k = 0; k < WAYS; k++) P[r][k] *= cs[k];
            }
        }
        if (CLAMP) {
            #pragma unroll
            for (int r = 0; r < RPT; r++) {
                int row = lane + 32*r;
                if (row < NSUP) {
                    int y = ys[b*NSUP + row];
                    #pragma unroll
                    for (int k = 0; k < WAYS; k++) P[r][k] = (k == y) ? 1.0f : 0.0f;
                }
            }
        }
        K++;
    }
    return K;
}

__global__ void k_sink1_count() {
    int gw = (blockIdx.x*blockDim.x + threadIdx.x) >> 5;
    int lane = threadIdx.x & 31;
    if (gw >= RUNS) return;
    float P[3][WAYS];
    const float* Mb = g_M + (size_t)gw*NEXTN*WAYS;
    #pragma unroll
    for (int r = 0; r < 3; r++) {
        int row = lane + 32*r;
        #pragma unroll
        for (int k = 0; k < WAYS; k++) P[r][k] = (row < NQ) ? Mb[row*WAYS + k] : 0.f;
    }
    int K = sink_iter<NQ, false>(P, gw, lane, nullptr, 15.0f, -1);
    if (lane == 0) atomicMax(&g_iters, K);
}

__global__ void k_sink1_apply(const int* __restrict__ ys) {
    int gw = (blockIdx.x*blockDim.x + threadIdx.x) >> 5;
    int lane = threadIdx.x & 31;
    if (gw >= RUNS) return;
    int b = gw;
    float P[3][WAYS];
    const float* Mb = g_M + (size_t)b*NEXTN*WAYS;
    #pragma unroll
    for (int r = 0; r < 3; r++) {
        int row = lane + 32*r;
        #pragma unroll
        for (int k = 0; k < WAYS; k++) P[r][k] = (row < NQ) ? Mb[row*WAYS + k] : 0.f;
    }
    int T = g_iters;
    sink_iter<NQ, false>(P, b, lane, nullptr, 15.0f, T);
    #pragma unroll
    for (int r = 0; r < 3; r++) {
        int row = lane + 32*r;
        if (row < NQ) {
            float e = entropy5(&P[r][0]);
            g_ent[b*NTOT + NSUP + row] = e;
            float wgt = 1.0f - e;
            #pragma unroll
            for (int k = 0; k < WAYS; k++)
                g_Z[((size_t)b*NEXTN + NSUP + row)*WAYS + k] = P[r][k]*wgt;
        }
    }
    if (lane < NSUP) {
        int y = ys[b*NSUP + lane];
        float v[5];
        #pragma unroll
        for (int k = 0; k < WAYS; k++) v[k] = (k == y) ? 1.0f : 0.0f;
        float e = entropy5(v);
        g_ent[b*NTOT + lane] = e;
        float wgt = 1.0f - e;
        #pragma unroll
        for (int k = 0; k < WAYS; k++)
            g_Z[((size_t)b*NEXTN + lane)*WAYS + k] = v[k]*wgt;
    }
}

__global__ void k_sink2_count(const int* __restrict__ ys) {
    int gw = (blockIdx.x*blockDim.x + threadIdx.x) >> 5;
    int lane = threadIdx.x & 31;
    if (gw >= RUNS) return;
    float P[4][WAYS];
    const float* Mb = g_M + (size_t)gw*NEXTN*WAYS;
    #pragma unroll
    for (int r = 0; r < 4; r++) {
        int row = lane + 32*r;
        #pragma unroll
        for (int k = 0; k < WAYS; k++) P[r][k] = (row < NEXTN) ? Mb[row*WAYS + k] : 0.f;
    }
    int K = sink_iter<NEXTN, true>(P, gw, lane, ys, 21.0f, -1);
    if (lane == 0) atomicMax(&g_iters, K);
}

__global__ void k_sink2_apply(const int* __restrict__ ys) {
    int gw = (blockIdx.x*blockDim.x + threadIdx.x) >> 5;
    int lane = threadIdx.x & 31;
    if (gw >= RUNS) return;
    int b = gw;
    float P[4][WAYS];
    const float* Mb = g_M + (size_t)b*NEXTN*WAYS;
    #pragma unroll
    for (int r = 0; r < 4; r++) {
        int row = lane + 32*r;
        #pragma unroll
        for (int k = 0; k < WAYS; k++) P[r][k] = (row < NEXTN) ? Mb[row*WAYS + k] : 0.f;
    }
    int T = g_iters;
    sink_iter<NEXTN, true>(P, b, lane, ys, 21.0f, T);
    #pragma unroll
    for (int r = 0; r < 4; r++) {
        int row = lane + 32*r;
        if (row < NEXTN) {
            #pragma unroll
            for (int k = 0; k < WAYS; k++)
                g_Z[((size_t)b*NEXTN + row)*WAYS + k] = P[r][k];
        }
    }
}

// ---------------- new_proto + proto EMA update ----------------
__global__ void k_newproto(const float* __restrict__ xs, const float* __restrict__ xq) {
    int b = blockIdx.x, t = threadIdx.x;  // 640 threads
    __shared__ float Zs[NTOT*WAYS];
    __shared__ float cs[WAYS];
    for (int idx = t; idx < NTOT*WAYS; idx += blockDim.x)
        Zs[idx] = g_Z[(size_t)b*NEXTN*WAYS + idx];
    __syncthreads();
    if (t < WAYS) {
        float s = 0.f;
        for (int n = 0; n < NTOT; n++) s += Zs[n*WAYS + t];
        cs[t] = s;
    }
    __syncthreads();
    float acc[WAYS] = {0,0,0,0,0};
    for (int n = 0; n < NTOT; n++) {
        float f = frow(xs, xq, b, n)[t];
        #pragma unroll
        for (int k = 0; k < WAYS; k++) acc[k] += Zs[n*WAYS + k]*f;
    }
    #pragma unroll
    for (int k = 0; k < WAYS; k++) {
        size_t pi = ((size_t)b*WAYS + k)*DD + t;
        float np = acc[k]/cs[k];
        g_proto[pi] = 0.4f*g_proto[pi] + 0.6f*np;
    }
}

// ---------------- epoch-2: proto mask, add_proto, Z extension ----------------
__global__ void k_mask() {
    int b = blockIdx.x, t = threadIdx.x;   // 160 threads
    int w = t >> 5, lane = t & 31;
    __shared__ float nrm[5], dp[5][5], score[5], mk[5], omega_s;
    const float* pr = g_proto + (size_t)b*WAYS*DD;
    {
        float a = 0.f;
        for (int d = lane; d < DD; d += 32) { float v = pr[w*DD + d]; a += v*v; }
        #pragma unroll
        for (int off = 16; off; off >>= 1) a += __shfl_xor_sync(0xffffffffu, a, off);
        if (lane == 0) nrm[w] = a;
    }
    __syncthreads();
    for (int j = 0; j < 5; j++) {
        float s = 0.f;
        for (int d = lane; d < DD; d += 32) s += pr[w*DD + d]*pr[j*DD + d];
        #pragma unroll
        for (int off = 16; off; off >>= 1) s += __shfl_xor_sync(0xffffffffu, s, off);
        if (lane == 0) {
            float d2 = fmaxf(nrm[w] + nrm[j] - 2.0f*s, 0.0f);
            dp[w][j] = expf(-10.0f*d2);
        }
    }
    __syncthreads();
    if (t < 5) score[t] = entropy5(&dp[t][0]);
    if (w == 1) {
        float s = 0.f;
        for (int i = lane; i < NTOT; i += 32) s += g_ent[b*NTOT + i];
        #pragma unroll
        for (int off = 16; off; off >>= 1) s += __shfl_xor_sync(0xffffffffu, s, off);
        if (lane == 0) omega_s = s / 100.0f;
    }
    __syncthreads();
    if (t < 5) mk[t] = (score[t] < omega_s) ? 1.0f : 0.0f;
    __syncthreads();
    for (int idx = t; idx < WAYS*DD; idx += 160) {
        int i = idx / DD, d = idx % DD;
        g_addp[((size_t)b*WAYS + i)*DD + d] = pr[i*DD + d]*mk[i];
    }
    if (t < 25) {
        int i = t / 5, k = t % 5;
        g_Z[((size_t)b*NEXTN + NTOT + i)*WAYS + k] = dp[i][k]*mk[i];
    }
}

// ---------------- squared norms of 105 feature rows ----------------
__global__ void k_sqn(const float* __restrict__ xs, const float* __restrict__ xq) {
    int b = blockIdx.x;
    int w = threadIdx.x >> 5, lane = threadIdx.x & 31;
    for (int row = w; row < NEXTN; row += 4) {
        const float* f = frow(xs, xq, b, row);
        float s = 0.f;
        for (int d = lane; d < DD; d += 32) { float v = f[d]; s += v*v; }
        #pragma unroll
        for (int off = 16; off; off >>= 1) s += __shfl_xor_sync(0xffffffffu, s, off);
        if (lane == 0) g_sqn[b*NEXTN + row] = s;
    }
}

// ---------------- 105x105 Gram -> W, 64 threads, 4x4 microtile ----------------
__global__ void __launch_bounds__(64) k_gram(const float* __restrict__ xs,
                                             const float* __restrict__ xq) {
    int b  = blockIdx.y;
    int ti = TIt[blockIdx.x], tj = TJt[blockIdx.x];
    int t  = threadIdx.x;             // 64 threads
    int tx = t & 7, ty = t >> 3;      // 8x8
    __shared__ float As[32][33], Bs[32][33];
    float acc[4][4] = {{0}};
    for (int dc = 0; dc < DD; dc += 32) {
        #pragma unroll
        for (int l = 0; l < 4; l++) {
            int id = t + l*64;              // 0..255
            int r = id >> 3, c4 = (id & 7)*4;
            int gi = ti*32 + r, gj = tj*32 + r;
            float4 av = make_float4(0,0,0,0), bv = make_float4(0,0,0,0);
            if (gi < NEXTN) av = *(const float4*)(frow(xs,xq,b,gi) + dc + c4);
            if (gj < NEXTN) bv = *(const float4*)(frow(xs,xq,b,gj) + dc + c4);
            As[r][c4+0]=av.x; As[r][c4+1]=av.y; As[r][c4+2]=av.z; As[r][c4+3]=av.w;
            Bs[r][c4+0]=bv.x; Bs[r][c4+1]=bv.y; Bs[r][c4+2]=bv.z; Bs[r][c4+3]=bv.w;
        }
        __syncthreads();
        #pragma unroll
        for (int kk = 0; kk < 32; kk++) {
            float a[4], bb[4];
            #pragma unroll
            for (int i = 0; i < 4; i++) a[i]  = As[ty*4+i][kk];
            #pragma unroll
            for (int j = 0; j < 4; j++) bb[j] = Bs[tx*4+j][kk];
            #pragma unroll
            for (int i = 0; i < 4; i++)
                #pragma unroll
                for (int j = 0; j < 4; j++)
                    acc[i][j] += a[i]*bb[j];
        }
        __syncthreads();
    }
    size_t Wb = (size_t)b*NEXTN*NEXTN;
    #pragma unroll
    for (int ii = 0; ii < 4; ii++)
    #pragma unroll
    for (int jj = 0; jj < 4; jj++) {
        int i = ti*32 + ty*4 + ii, j = tj*32 + tx*4 + jj;
        if (i < NEXTN && j < NEXTN) {
            float d2 = g_sqn[b*NEXTN + i] + g_sqn[b*NEXTN + j] - 2.0f*acc[ii][jj];
            d2 = fmaxf(d2, 0.0f);
            float wv = (i == j) ? 0.0f : expf(-10.0f*d2);
            g_W[Wb + (size_t)i*NEXTN + j] = wv;
            if (ti != tj) g_W[Wb + (size_t)j*NEXTN + i] = wv;
        }
    }
}

// ---------------- Dm = rowsum^-1/2 ----------------
__global__ void k_dm() {
    int b = blockIdx.x;
    int w = threadIdx.x >> 5, lane = threadIdx.x & 31;
    for (int row = w; row < NEXTN; row += 4) {
        const float* Wr = g_W + (size_t)b*NEXTN*NEXTN + (size_t)row*NEXTN;
        float s = 0.f;
        for (int j = lane; j < NEXTN; j += 32) s += Wr[j];
        #pragma unroll
        for (int off = 16; off; off >>= 1) s += __shfl_xor_sync(0xffffffffu, s, off);
        if (lane == 0) g_dm[b*NEXTN + row] = 1.0f/sqrtf(s);
    }
}

// ---------------- solve (I - 0.7 * Dm W Dm) X = Z  -> g_M ----------------
__global__ void __launch_bounds__(128) k_solve() {
    int b = blockIdx.x, t = threadIdx.x;
    __shared__ float A[NEXTN*LDA];
    const float* Wb = g_W + (size_t)b*NEXTN*NEXTN;
    const float* dm = g_dm + b*NEXTN;
    for (int idx = t; idx < NEXTN*NEXTN; idx += 128) {
        int i = idx/NEXTN, j = idx%NEXTN;
        float wn = dm[i]*Wb[idx]*dm[j];
        A[i*LDA + j] = ((i == j) ? 1.0f : 0.0f) - 0.7f*wn;
    }
    for (int idx = t; idx < NEXTN*WAYS; idx += 128) {
        int i = idx/WAYS, k = idx%WAYS;
        A[i*LDA + NEXTN + k] = g_Z[((size_t)b*NEXTN + i)*WAYS + k];
    }
    __syncthreads();
    for (int k = 0; k < NEXTN; k++) {
        if (t < NEXTN && t != k) {
            float f = A[t*LDA + k] / A[k*LDA + k];
            for (int j = k+1; j < NEXTN + WAYS; j++)
                A[t*LDA + j] -= f*A[k*LDA + j];
        }
        __syncthreads();
    }
    for (int idx = t; idx < NEXTN*WAYS; idx += 128) {
        int i = idx/WAYS, k = idx%WAYS;
        g_M[((size_t)b*NEXTN + i)*WAYS + k] = A[i*LDA + NEXTN + k] / A[i*LDA + i];
    }
}

// ---------------- predict ----------------
__global__ void k_predict(const int* __restrict__ yq, float* __restrict__ out) {
    int gw = (blockIdx.x*blockDim.x + threadIdx.x) >> 5;
    int lane = threadIdx.x & 31;
    if (gw >= RUNS) return;
    int cnt = 0;
    for (int q = lane; q < NQ; q += 32) {
        const float* z = g_Z + ((size_t)gw*NEXTN + NSUP + q)*WAYS;
        int am = 0; float bv = z[0];
        #pragma unroll
        for (int k = 1; k < 5; k++) { float v = z[k]; if (v > bv) { bv = v; am = k; } }
        cnt += (am == yq[gw*NQ + q]) ? 1 : 0;
    }
    #pragma unroll
    for (int off = 16; off; off >>= 1) cnt += __shfl_xor_sync(0xffffffffu, cnt, off);
    if (lane == 0) out[gw] = (float)cnt / 75.0f;
}

extern "C" void kernel_launch(void* const* d_in, const int* in_sizes, int n_in,
                              void* d_out, int out_size) {
    const float* xs = (const float*)d_in[0];
    const float* xq = (const float*)d_in[1];
    const int*   ys = (const int*)d_in[2];
    const int*   yq = (const int*)d_in[3];
    float* out = (float*)d_out;

    k_proto_init<<<RUNS, DD>>>(xs);
    for (int e = 0; e < 3; e++) {
        k_pq<<<(RUNS*NQ*32 + 255)/256, 256>>>(xq);
        k_reset<<<1, 1>>>();
        k_sink1_count<<<(RUNS*32 + 255)/256, 256>>>();
        k_sink1_apply<<<(RUNS*32 + 255)/256, 256>>>(ys);
        k_newproto<<<RUNS, DD>>>(xs, xq);
        if (e == 2) {
            k_mask<<<RUNS, 160>>>();
            k_sqn<<<RUNS, 128>>>(xs, xq);
            k_gram<<<dim3(10, RUNS), 64>>>(xs, xq);
            k_dm<<<RUNS, 128>>>();
            k_solve<<<RUNS, 128>>>();
            k_reset<<<1, 1>>>();
            k_sink2_count<<<(RUNS*32 + 255)/256, 256>>>(ys);
            k_sink2_apply<<<(RUNS*32 + 255)/256, 256>>>(ys);
            k_predict<<<(RUNS*32 + 255)/256, 256>>>(yq, out);
        }
    }
}

// round 7
// speedup vs baseline: 2.6345x; 1.0467x over previous
#include <cuda_runtime.h>
#include <math.h>

#define RUNS 512
#define WAYS 5
#define NSUP 25
#define NQ   75
#define NTOT 100
#define NEXTN 105
#define DD   640
#define EPSf 0.001f
#define LDA 114   // even stride: float2 conflict-free (18-bank stride over 16-lane phase)

// ---------------- device scratch (static, no allocation) ----------------
__device__ float g_proto[RUNS*WAYS*DD];
__device__ float g_addp [RUNS*WAYS*DD];
__device__ float g_M [RUNS*NEXTN*WAYS];   // sinkhorn input
__device__ float g_Z [RUNS*NEXTN*WAYS];   // current Z
__device__ float g_ent[RUNS*NTOT];
__device__ float g_W [RUNS*NEXTN*NEXTN];  // graph weights
__device__ float g_sqn[RUNS*NEXTN];       // squared norms of features105
__device__ int   g_iters;

__constant__ int TIt[10] = {0,0,0,0,1,1,1,2,2,3};
__constant__ int TJt[10] = {0,1,2,3,1,2,3,2,3,3};

// ---------------- helpers ----------------
__device__ __forceinline__ const float* frow(const float* xs, const float* xq, int b, int i) {
    if (i < NSUP) return xs + ((size_t)b*NSUP + i)*DD;
    if (i < NTOT) return xq + ((size_t)b*NQ + (i-NSUP))*DD;
    return g_addp + ((size_t)b*WAYS + (i-NTOT))*DD;
}

__device__ __forceinline__ float entropy5(const float* v) {
    float p[5]; float s = 0.f;
    #pragma unroll
    for (int k = 0; k < 5; k++) { p[k] = v[k] + 1e-12f; s += p[k]; }
    float H = 0.f;
    #pragma unroll
    for (int k = 0; k < 5; k++) { float q = p[k]/s; H -= q*logf(q); }
    return H / logf(5.0f);
}

// ---------------- proto init: mean over shots ----------------
__global__ void k_proto_init(const float* __restrict__ xs) {
    int b = blockIdx.x, d = threadIdx.x;   // 640 threads
    #pragma unroll
    for (int k = 0; k < WAYS; k++) {
        float s = 0.f;
        #pragma unroll
        for (int sh = 0; sh < 5; sh++) s += xs[((size_t)b*NSUP + k*5 + sh)*DD + d];
        g_proto[((size_t)b*WAYS + k)*DD + d] = s / 5.0f;
    }
}

// ---------------- Pq = exp(-10 * d2(query, proto)), block per run ----------------
__global__ void __launch_bounds__(256) k_pq(const float* __restrict__ xq) {
    int b = blockIdx.x, t = threadIdx.x;
    int w = t >> 5, lane = t & 31;
    __shared__ float ps[WAYS*DD];
    __shared__ float pp[WAYS];
    const float* pr = g_proto + (size_t)b*WAYS*DD;
    for (int i = t; i < WAYS*DD/4; i += 256)
        ((float4*)ps)[i] = ((const float4*)pr)[i];
    __syncthreads();
    if (w < WAYS) {
        float s = 0.f;
        for (int d = lane; d < DD; d += 32) { float v = ps[w*DD + d]; s += v*v; }
        #pragma unroll
        for (int off = 16; off; off >>= 1) s += __shfl_xor_sync(0xffffffffu, s, off);
        if (lane == 0) pp[w] = s;
    }
    __syncthreads();
    for (int q = w; q < NQ; q += 8) {
        const float* x = xq + ((size_t)b*NQ + q)*DD;
        float dot[5] = {0,0,0,0,0}, qq = 0.f;
        for (int d = lane; d < DD; d += 32) {
            float xv = x[d];
            qq += xv*xv;
            #pragma unroll
            for (int k = 0; k < 5; k++) dot[k] += xv*ps[k*DD + d];
        }
        #pragma unroll
        for (int off = 16; off; off >>= 1) {
            qq += __shfl_xor_sync(0xffffffffu, qq, off);
            #pragma unroll
            for (int k = 0; k < 5; k++)
                dot[k] += __shfl_xor_sync(0xffffffffu, dot[k], off);
        }
        if (lane == 0) {
            #pragma unroll
            for (int k = 0; k < 5; k++) {
                float d2 = fmaxf(qq + pp[k] - 2.0f*dot[k], 0.0f);
                g_M[((size_t)b*NEXTN + q)*WAYS + k] = expf(-10.0f*d2);
            }
        }
    }
}

__global__ void k_reset() { g_iters = 0; }

// ---------------- warp-resident sinkhorn ----------------
template<int N, bool CLAMP>
__device__ __forceinline__ int sink_iter(float (&P)[(N+31)/32][WAYS], int b, int lane,
                                         const int* ys, float Cval, int T) {
    const int RPT = (N+31)/32;
    float u[RPT];
    #pragma unroll
    for (int r = 0; r < RPT; r++) u[r] = 0.f;
    int K = 0;
    while (true) {
        if (T >= 0 && K >= T) break;
        float rs[RPT];
        #pragma unroll
        for (int r = 0; r < RPT; r++) {
            int row = lane + 32*r;
            rs[r] = (row < N) ? ((((P[r][0]+P[r][1])+P[r][2])+P[r][3])+P[r][4]) : 0.f;
        }
        if (T < 0) {
            float rm = 0.f;
            #pragma unroll
            for (int r = 0; r < RPT; r++) {
                int row = lane + 32*r;
                if (row < N) rm = fmaxf(rm, fabsf(u[r]-rs[r]));
            }
            #pragma unroll
            for (int off = 16; off; off >>= 1)
                rm = fmaxf(rm, __shfl_xor_sync(0xffffffffu, rm, off));
            if (rm <= EPSf || K >= 1000) break;
            #pragma unroll
            for (int r = 0; r < RPT; r++) u[r] = rs[r];
        }
        #pragma unroll
        for (int r = 0; r < RPT; r++) {
            int row = lane + 32*r;
            if (row < N) {
                float inv = 1.0f/rs[r];
                #pragma unroll
                for (int k = 0; k < WAYS; k++) P[r][k] *= inv;
            }
        }
        float cs[WAYS];
        #pragma unroll
        for (int k = 0; k < WAYS; k++) cs[k] = 0.f;
        #pragma unroll
        for (int r = 0; r < RPT; r++) {
            int row = lane + 32*r;
            if (row < N) {
                #pragma unroll
                for (int k = 0; k < WAYS; k++) cs[k] += P[r][k];
            }
        }
        #pragma unroll
        for (int off = 16; off; off >>= 1) {
            #pragma unroll
            for (int k = 0; k < WAYS; k++)
                cs[k] += __shfl_xor_sync(0xffffffffu, cs[k], off);
        }
        #pragma unroll
        for (int k = 0; k < WAYS; k++) cs[k] = Cval/cs[k];
        #pragma unroll
        for (int r = 0; r < RPT; r++) {
            int row = lane + 32*r;
            if (row < N) {
                #pragma unroll
                for (int k = 0; k < WAYS; k++) P[r][k] *= cs[k];
            }
        }
        if (CLAMP) {
            #pragma unroll
            for (int r = 0; r < RPT; r++) {
                int row = lane + 32*r;
                if (row < NSUP) {
                    int y = ys[b*NSUP + row];
                    #pragma unroll
                    for (int k = 0; k < WAYS; k++) P[r][k] = (k == y) ? 1.0f : 0.0f;
                }
            }
        }
        K++;
    }
    return K;
}

__global__ void k_sink1_count() {
    int gw = (blockIdx.x*blockDim.x + threadIdx.x) >> 5;
    int lane = threadIdx.x & 31;
    if (gw >= RUNS) return;
    float P[3][WAYS];
    const float* Mb = g_M + (size_t)gw*NEXTN*WAYS;
    #pragma unroll
    for (int r = 0; r < 3; r++) {
        int row = lane + 32*r;
        #pragma unroll
        for (int k = 0; k < WAYS; k++) P[r][k] = (row < NQ) ? Mb[row*WAYS + k] : 0.f;
    }
    int K = sink_iter<NQ, false>(P, gw, lane, nullptr, 15.0f, -1);
    if (lane == 0) atomicMax(&g_iters, K);
}

__global__ void k_sink1_apply(const int* __restrict__ ys) {
    int gw = (blockIdx.x*blockDim.x + threadIdx.x) >> 5;
    int lane = threadIdx.x & 31;
    if (gw >= RUNS) return;
    int b = gw;
    float P[3][WAYS];
    const float* Mb = g_M + (size_t)b*NEXTN*WAYS;
    #pragma unroll
    for (int r = 0; r < 3; r++) {
        int row = lane + 32*r;
        #pragma unroll
        for (int k = 0; k < WAYS; k++) P[r][k] = (row < NQ) ? Mb[row*WAYS + k] : 0.f;
    }
    int T = g_iters;
    sink_iter<NQ, false>(P, b, lane, nullptr, 15.0f, T);
    #pragma unroll
    for (int r = 0; r < 3; r++) {
        int row = lane + 32*r;
        if (row < NQ) {
            float e = entropy5(&P[r][0]);
            g_ent[b*NTOT + NSUP + row] = e;
            float wgt = 1.0f - e;
            #pragma unroll
            for (int k = 0; k < WAYS; k++)
                g_Z[((size_t)b*NEXTN + NSUP + row)*WAYS + k] = P[r][k]*wgt;
        }
    }
    if (lane < NSUP) {
        int y = ys[b*NSUP + lane];
        float v[5];
        #pragma unroll
        for (int k = 0; k < WAYS; k++) v[k] = (k == y) ? 1.0f : 0.0f;
        float e = entropy5(v);
        g_ent[b*NTOT + lane] = e;
        float wgt = 1.0f - e;
        #pragma unroll
        for (int k = 0; k < WAYS; k++)
            g_Z[((size_t)b*NEXTN + lane)*WAYS + k] = v[k]*wgt;
    }
}

__global__ void k_sink2_count(const int* __restrict__ ys) {
    int gw = (blockIdx.x*blockDim.x + threadIdx.x) >> 5;
    int lane = threadIdx.x & 31;
    if (gw >= RUNS) return;
    float P[4][WAYS];
    const float* Mb = g_M + (size_t)gw*NEXTN*WAYS;
    #pragma unroll
    for (int r = 0; r < 4; r++) {
        int row = lane + 32*r;
        #pragma unroll
        for (int k = 0; k < WAYS; k++) P[r][k] = (row < NEXTN) ? Mb[row*WAYS + k] : 0.f;
    }
    int K = sink_iter<NEXTN, true>(P, gw, lane, ys, 21.0f, -1);
    if (lane == 0) atomicMax(&g_iters, K);
}

__global__ void k_sink2_apply(const int* __restrict__ ys) {
    int gw = (blockIdx.x*blockDim.x + threadIdx.x) >> 5;
    int lane = threadIdx.x & 31;
    if (gw >= RUNS) return;
    int b = gw;
    float P[4][WAYS];
    const float* Mb = g_M + (size_t)b*NEXTN*WAYS;
    #pragma unroll
    for (int r = 0; r < 4; r++) {
        int row = lane + 32*r;
        #pragma unroll
        for (int k = 0; k < WAYS; k++) P[r][k] = (row < NEXTN) ? Mb[row*WAYS + k] : 0.f;
    }
    int T = g_iters;
    sink_iter<NEXTN, true>(P, b, lane, ys, 21.0f, T);
    #pragma unroll
    for (int r = 0; r < 4; r++) {
        int row = lane + 32*r;
        if (row < NEXTN) {
            #pragma unroll
            for (int k = 0; k < WAYS; k++)
                g_Z[((size_t)b*NEXTN + row)*WAYS + k] = P[r][k];
        }
    }
}

// ---------------- new_proto + proto EMA update ----------------
__global__ void k_newproto(const float* __restrict__ xs, const float* __restrict__ xq) {
    int b = blockIdx.x, t = threadIdx.x;  // 640 threads
    __shared__ float Zs[NTOT*WAYS];
    __shared__ float cs[WAYS];
    for (int idx = t; idx < NTOT*WAYS; idx += blockDim.x)
        Zs[idx] = g_Z[(size_t)b*NEXTN*WAYS + idx];
    __syncthreads();
    if (t < WAYS) {
        float s = 0.f;
        for (int n = 0; n < NTOT; n++) s += Zs[n*WAYS + t];
        cs[t] = s;
    }
    __syncthreads();
    float acc[WAYS] = {0,0,0,0,0};
    for (int n = 0; n < NTOT; n++) {
        float f = frow(xs, xq, b, n)[t];
        #pragma unroll
        for (int k = 0; k < WAYS; k++) acc[k] += Zs[n*WAYS + k]*f;
    }
    #pragma unroll
    for (int k = 0; k < WAYS; k++) {
        size_t pi = ((size_t)b*WAYS + k)*DD + t;
        float np = acc[k]/cs[k];
        g_proto[pi] = 0.4f*g_proto[pi] + 0.6f*np;
    }
}

// ---------------- epoch-2: proto mask, add_proto, Z extension ----------------
__global__ void k_mask() {
    int b = blockIdx.x, t = threadIdx.x;   // 160 threads
    int w = t >> 5, lane = t & 31;
    __shared__ float nrm[5], dp[5][5], score[5], mk[5], omega_s;
    const float* pr = g_proto + (size_t)b*WAYS*DD;
    {
        float a = 0.f;
        for (int d = lane; d < DD; d += 32) { float v = pr[w*DD + d]; a += v*v; }
        #pragma unroll
        for (int off = 16; off; off >>= 1) a += __shfl_xor_sync(0xffffffffu, a, off);
        if (lane == 0) nrm[w] = a;
    }
    __syncthreads();
    for (int j = 0; j < 5; j++) {
        float s = 0.f;
        for (int d = lane; d < DD; d += 32) s += pr[w*DD + d]*pr[j*DD + d];
        #pragma unroll
        for (int off = 16; off; off >>= 1) s += __shfl_xor_sync(0xffffffffu, s, off);
        if (lane == 0) {
            float d2 = fmaxf(nrm[w] + nrm[j] - 2.0f*s, 0.0f);
            dp[w][j] = expf(-10.0f*d2);
        }
    }
    __syncthreads();
    if (t < 5) score[t] = entropy5(&dp[t][0]);
    if (w == 1) {
        float s = 0.f;
        for (int i = lane; i < NTOT; i += 32) s += g_ent[b*NTOT + i];
        #pragma unroll
        for (int off = 16; off; off >>= 1) s += __shfl_xor_sync(0xffffffffu, s, off);
        if (lane == 0) omega_s = s / 100.0f;
    }
    __syncthreads();
    if (t < 5) mk[t] = (score[t] < omega_s) ? 1.0f : 0.0f;
    __syncthreads();
    for (int idx = t; idx < WAYS*DD; idx += 160) {
        int i = idx / DD, d = idx % DD;
        g_addp[((size_t)b*WAYS + i)*DD + d] = pr[i*DD + d]*mk[i];
    }
    if (t < 25) {
        int i = t / 5, k = t % 5;
        g_Z[((size_t)b*NEXTN + NTOT + i)*WAYS + k] = dp[i][k]*mk[i];
    }
}

// ---------------- squared norms of 105 feature rows ----------------
__global__ void k_sqn(const float* __restrict__ xs, const float* __restrict__ xq) {
    int b = blockIdx.x;
    int w = threadIdx.x >> 5, lane = threadIdx.x & 31;
    for (int row = w; row < NEXTN; row += 4) {
        const float* f = frow(xs, xq, b, row);
        float s = 0.f;
        for (int d = lane; d < DD; d += 32) { float v = f[d]; s += v*v; }
        #pragma unroll
        for (int off = 16; off; off >>= 1) s += __shfl_xor_sync(0xffffffffu, s, off);
        if (lane == 0) g_sqn[b*NEXTN + row] = s;
    }
}

// ---------------- 105x105 Gram -> W, 64 threads, 4x4 microtile ----------------
__global__ void __launch_bounds__(64) k_gram(const float* __restrict__ xs,
                                             const float* __restrict__ xq) {
    int b  = blockIdx.y;
    int ti = TIt[blockIdx.x], tj = TJt[blockIdx.x];
    int t  = threadIdx.x;             // 64 threads
    int tx = t & 7, ty = t >> 3;      // 8x8
    __shared__ float As[32][33], Bs[32][33];
    float acc[4][4] = {{0}};
    for (int dc = 0; dc < DD; dc += 32) {
        #pragma unroll
        for (int l = 0; l < 4; l++) {
            int id = t + l*64;              // 0..255
            int r = id >> 3, c4 = (id & 7)*4;
            int gi = ti*32 + r, gj = tj*32 + r;
            float4 av = make_float4(0,0,0,0), bv = make_float4(0,0,0,0);
            if (gi < NEXTN) av = *(const float4*)(frow(xs,xq,b,gi) + dc + c4);
            if (gj < NEXTN) bv = *(const float4*)(frow(xs,xq,b,gj) + dc + c4);
            As[r][c4+0]=av.x; As[r][c4+1]=av.y; As[r][c4+2]=av.z; As[r][c4+3]=av.w;
            Bs[r][c4+0]=bv.x; Bs[r][c4+1]=bv.y; Bs[r][c4+2]=bv.z; Bs[r][c4+3]=bv.w;
        }
        __syncthreads();
        #pragma unroll
        for (int kk = 0; kk < 32; kk++) {
            float a[4], bb[4];
            #pragma unroll
            for (int i = 0; i < 4; i++) a[i]  = As[ty*4+i][kk];
            #pragma unroll
            for (int j = 0; j < 4; j++) bb[j] = Bs[tx*4+j][kk];
            #pragma unroll
            for (int i = 0; i < 4; i++)
                #pragma unroll
                for (int j = 0; j < 4; j++)
                    acc[i][j] += a[i]*bb[j];
        }
        __syncthreads();
    }
    size_t Wb = (size_t)b*NEXTN*NEXTN;
    #pragma unroll
    for (int ii = 0; ii < 4; ii++)
    #pragma unroll
    for (int jj = 0; jj < 4; jj++) {
        int i = ti*32 + ty*4 + ii, j = tj*32 + tx*4 + jj;
        if (i < NEXTN && j < NEXTN) {
            float d2 = g_sqn[b*NEXTN + i] + g_sqn[b*NEXTN + j] - 2.0f*acc[ii][jj];
            d2 = fmaxf(d2, 0.0f);
            float wv = (i == j) ? 0.0f : expf(-10.0f*d2);
            g_W[Wb + (size_t)i*NEXTN + j] = wv;
            if (ti != tj) g_W[Wb + (size_t)j*NEXTN + i] = wv;
        }
    }
}

// ------- solve (I - 0.7 * Dm W Dm) X = Z -> g_M  (dm fused, float2 update) -------
__global__ void __launch_bounds__(128) k_solve() {
    int b = blockIdx.x, t = threadIdx.x;
    __shared__ float A[NEXTN*LDA];
    __shared__ float dm[NEXTN];
    const float* Wb = g_W + (size_t)b*NEXTN*NEXTN;
    // load raw W
    for (int idx = t; idx < NEXTN*NEXTN; idx += 128) {
        int i = idx/NEXTN, j = idx%NEXTN;
        A[i*LDA + j] = Wb[idx];
    }
    __syncthreads();
    // row sums -> dm
    if (t < NEXTN) {
        float s = 0.f;
        for (int j = 0; j < NEXTN; j++) s += A[t*LDA + j];
        dm[t] = rsqrtf(s);
    }
    __syncthreads();
    // A = I - 0.7 * dm_i * W * dm_j ; RHS in cols 105..109
    if (t < NEXTN) {
        float di = 0.7f*dm[t];
        for (int j = 0; j < NEXTN; j++) {
            float v = di*dm[j]*A[t*LDA + j];
            A[t*LDA + j] = ((t == j) ? 1.0f : 0.0f) - v;
        }
        #pragma unroll
        for (int k = 0; k < WAYS; k++)
            A[t*LDA + NEXTN + k] = g_Z[((size_t)b*NEXTN + t)*WAYS + k];
    }
    __syncthreads();
    // Gauss-Jordan, float2 inner
    for (int k = 0; k < NEXTN; k++) {
        if (t < NEXTN && t != k) {
            float f = A[t*LDA + k] / A[k*LDA + k];
            int j = k + 1;
            if (j & 1) { A[t*LDA + j] -= f*A[k*LDA + j]; j++; }
            for (; j < NEXTN + WAYS; j += 2) {
                float2 pv = *(const float2*)&A[k*LDA + j];
                float2 av = *(float2*)&A[t*LDA + j];
                av.x -= f*pv.x; av.y -= f*pv.y;
                *(float2*)&A[t*LDA + j] = av;
            }
        }
        __syncthreads();
    }
    if (t < NEXTN) {
        float inv = 1.0f / A[t*LDA + t];
        #pragma unroll
        for (int k = 0; k < WAYS; k++)
            g_M[((size_t)b*NEXTN + t)*WAYS + k] = A[t*LDA + NEXTN + k]*inv;
    }
}

// ---------------- predict ----------------
__global__ void k_predict(const int* __restrict__ yq, float* __restrict__ out) {
    int gw = (blockIdx.x*blockDim.x + threadIdx.x) >> 5;
    int lane = threadIdx.x & 31;
    if (gw >= RUNS) return;
    int cnt = 0;
    for (int q = lane; q < NQ; q += 32) {
        const float* z = g_Z + ((size_t)gw*NEXTN + NSUP + q)*WAYS;
        int am = 0; float bv = z[0];
        #pragma unroll
        for (int k = 1; k < 5; k++) { float v = z[k]; if (v > bv) { bv = v; am = k; } }
        cnt += (am == yq[gw*NQ + q]) ? 1 : 0;
    }
    #pragma unroll
    for (int off = 16; off; off >>= 1) cnt += __shfl_xor_sync(0xffffffffu, cnt, off);
    if (lane == 0) out[gw] = (float)cnt / 75.0f;
}

extern "C" void kernel_launch(void* const* d_in, const int* in_sizes, int n_in,
                              void* d_out, int out_size) {
    const float* xs = (const float*)d_in[0];
    const float* xq = (const float*)d_in[1];
    const int*   ys = (const int*)d_in[2];
    const int*   yq = (const int*)d_in[3];
    float* out = (float*)d_out;

    k_proto_init<<<RUNS, DD>>>(xs);
    for (int e = 0; e < 3; e++) {
        k_pq<<<RUNS, 256>>>(xq);
        k_reset<<<1, 1>>>();
        k_sink1_count<<<(RUNS*32 + 255)/256, 256>>>();
        k_sink1_apply<<<(RUNS*32 + 255)/256, 256>>>(ys);
        k_newproto<<<RUNS, DD>>>(xs, xq);
        if (e == 2) {
            k_mask<<<RUNS, 160>>>();
            k_sqn<<<RUNS, 128>>>(xs, xq);
            k_gram<<<dim3(10, RUNS), 64>>>(xs, xq);
            k_solve<<<RUNS, 128>>>();
            k_reset<<<1, 1>>>();
            k_sink2_count<<<(RUNS*32 + 255)/256, 256>>>(ys);
            k_sink2_apply<<<(RUNS*32 + 255)/256, 256>>>(ys);
            k_predict<<<(RUNS*32 + 255)/256, 256>>>(yq, out);
        }
    }
}